// round 1
// baseline (speedup 1.0000x reference)
#include <cuda_runtime.h>
#include <cuda_bf16.h>
#include <stdint.h>

// Problem shape (fixed by the dataset):
//   updates: (8,128,128,256) float32  -> 33,554,432 elements
//   mask:    same shape int32, values in [0, 16,777,216)
//   output:  (8,256,256,256) float32  -> 134,217,728 elements
// flat_input_size  = 128*128*256 = 4,194,304  (batch offset stride!)
// out[mask[i] + (i / 4194304)*4194304] += updates[i], rest zeros.

#define N_ELEMS      33554432
#define N_VEC4       (N_ELEMS / 4)          // 8,388,608 float4/int4
#define BATCH_V4_SH  20                     // 4,194,304/4 = 2^20 vec4 per batch
#define BATCH_OFF_SH 22                     // 4,194,304 = 2^22 element batch offset

__global__ __launch_bounds__(256, 8)
void scatter_add_kernel(const float4* __restrict__ upd4,
                        const int4*  __restrict__ msk4,
                        float* __restrict__ out)
{
    unsigned int i = blockIdx.x * 256u + threadIdx.x;
    if (i >= N_VEC4) return;

    // Batch base offset in output elements: (i >> 20) << 22
    unsigned int base = (i >> BATCH_V4_SH) << BATCH_OFF_SH;

    float4 u = upd4[i];
    int4   m = msk4[i];

    // atomicAdd with ignored return -> RED.E.ADD.F32 (no return latency)
    atomicAdd(out + base + (unsigned int)m.x, u.x);
    atomicAdd(out + base + (unsigned int)m.y, u.y);
    atomicAdd(out + base + (unsigned int)m.z, u.z);
    atomicAdd(out + base + (unsigned int)m.w, u.w);
}

extern "C" void kernel_launch(void* const* d_in, const int* in_sizes, int n_in,
                              void* d_out, int out_size)
{
    const float4* upd4 = (const float4*)d_in[0];
    const int4*   msk4 = (const int4*)d_in[1];
    float* out = (float*)d_out;

    // Zero the output (poisoned to 0xAA by the harness). Memset node is
    // graph-capturable and stream-ordered before the scatter kernel.
    cudaMemsetAsync(d_out, 0, (size_t)out_size * sizeof(float), 0);

    const int threads = 256;
    const int blocks  = (N_VEC4 + threads - 1) / threads;  // 32768 blocks
    scatter_add_kernel<<<blocks, threads>>>(upd4, msk4, out);
}